// round 11
// baseline (speedup 1.0000x reference)
#include <cuda_runtime.h>
#include <cuda_bf16.h>

#define FULL_MASK 0xFFFFFFFFu

constexpr int B_ROWS     = 16384;
constexpr int SEQ_L      = 50;
constexpr int N_SUBJECTS = 10000;
constexpr int N_ITER     = 25;      // 25 * 2 groups = 50 positions exactly

// Augmented bf16 table, one 64B row per subject (64B-aligned -> every row
// lies inside ONE 128B line):
//   bytes [0,32):  escore_j * emb_j  as 16 bf16   (dims 2c,2c+1 in word c)
//   bytes [32,34): escore_j as bf16
//   bytes [34,64): zeros
// escore_j = exp(dot(emb_j, w) + b); escore_0 := 0 so PAD (idx 0)
// contributes 0 to numerator AND denominator.
// Softmax without max-subtraction is exact: scores are O(0.1)
// (emb ~0.1*N, w ~0.25*N, D=16) -> no fp32 overflow; shift-invariant.
__device__ __align__(128) uint4 g_tab[N_SUBJECTS * 4];

__device__ __forceinline__ float dot4(float4 a, float4 b) {
    return a.x * b.x + a.y * b.y + a.z * b.z + a.w * b.w;
}

// ---------------- Prologue: build augmented bf16 table ----------------
__global__ void __launch_bounds__(256)
tab_kernel(const float* __restrict__ subj_emb,
           const float* __restrict__ attn_w,
           const float* __restrict__ attn_b)
{
    const int j = blockIdx.x * blockDim.x + threadIdx.x;
    if (j >= N_SUBJECTS) return;

    const float4* wp = reinterpret_cast<const float4*>(attn_w);
    const float4 w0 = __ldg(wp + 0), w1 = __ldg(wp + 1),
                 w2 = __ldg(wp + 2), w3 = __ldg(wp + 3);

    const float4* ep = reinterpret_cast<const float4*>(subj_emb) + (size_t)j * 4;
    const float4 e0 = __ldg(ep + 0), e1 = __ldg(ep + 1),
                 e2 = __ldg(ep + 2), e3 = __ldg(ep + 3);

    const float s = dot4(e0, w0) + dot4(e1, w1) + dot4(e2, w2) + dot4(e3, w3)
                  + __ldg(attn_b);
    const float w = (j == 0) ? 0.0f : __expf(s);

    const float4 p0 = make_float4(w*e0.x, w*e0.y, w*e0.z, w*e0.w);
    const float4 p1 = make_float4(w*e1.x, w*e1.y, w*e1.z, w*e1.w);
    const float4 p2 = make_float4(w*e2.x, w*e2.y, w*e2.z, w*e2.w);
    const float4 p3 = make_float4(w*e3.x, w*e3.y, w*e3.z, w*e3.w);

    auto pack2 = [](float a, float b) -> unsigned {
        __nv_bfloat162 h = __floats2bfloat162_rn(a, b);
        return *reinterpret_cast<unsigned*>(&h);
    };

    uint4* dst = g_tab + (size_t)j * 4;
    dst[0] = make_uint4(pack2(p0.x,p0.y), pack2(p0.z,p0.w),
                        pack2(p1.x,p1.y), pack2(p1.z,p1.w));
    dst[1] = make_uint4(pack2(p2.x,p2.y), pack2(p2.z,p2.w),
                        pack2(p3.x,p3.y), pack2(p3.z,p3.w));
    dst[2] = make_uint4(pack2(w, 0.f), 0u, 0u, 0u);   // escore slot
    dst[3] = make_uint4(0u, 0u, 0u, 0u);
}

// ---------------- Main: warp per row, 2 groups x 16 lanes ----------------
// Group g = lane>>4 handles positions p = it*2 + g. Lane c = lane&15 does
// ONE LDG.32 (4B) of word c of the 64B row: the 16 lanes of a group cover
// one row = ONE 128B line -> only 2 distinct lines per LDG instruction
// (1 + 1 replay wavefront, vs 1 + 3 for the 8-lane/LDG.64 variant).
//   c 0..7  -> premult dims (2c, 2c+1) as bf16x2
//   c == 8  -> (escore, 0)
//   c 9..15 -> zeros (uniform code, contribute nothing)
// Loop kept ROLLED (unroll 5) with minimal live state so registers stay
// ~40 and occupancy >= 70% (R10's full unroll hit 74 regs / 32% occ).
__global__ void __launch_bounds__(256, 6)
scalar_pooler_kernel(
    const float* __restrict__ user_bias,
    const float* __restrict__ item_bias,
    const float* __restrict__ global_bias,
    const int*   __restrict__ user_idx,
    const int*   __restrict__ item_idx,
    const int*   __restrict__ fav,
    const int*   __restrict__ book,
    float*       __restrict__ out)
{
    const int row  = (blockIdx.x * blockDim.x + threadIdx.x) >> 5;
    const int lane = threadIdx.x & 31;
    const int g    = lane >> 4;                    // 0..1
    const int c    = lane & 15;                    // 0..15
    if (row >= B_ROWS) return;

    const char* tab = reinterpret_cast<const char*>(g_tab);
    const int coff  = c * 4;

    const int* frow = fav  + (size_t)row * SEQ_L;
    const int* brow = book + (size_t)row * SEQ_L;

    // Coalesced index preload: lane holds positions lane and lane+32.
    const int f_lo = __ldg(frow + lane);
    const int f_hi = (lane + 32 < SEQ_L) ? __ldg(frow + lane + 32) : 0;
    const int b_lo = __ldg(brow + lane);
    const int b_hi = (lane + 32 < SEQ_L) ? __ldg(brow + lane + 32) : 0;

    float2 au = make_float2(0.f, 0.f);
    float2 ai = make_float2(0.f, 0.f);

    #pragma unroll 5
    for (int it = 0; it < N_ITER; it++) {
        // Position p = it*2 + g; source lane = p mod 32, register by p < 32.
        const int p   = it * 2 + g;
        const int lo  = (it < 16);                 // p<32 <=> it<16 for g in {0,1}
        const int src = p - (lo ? 0 : 32);
        const int iu  = __shfl_sync(FULL_MASK, lo ? f_lo : f_hi, src);
        const int ib  = __shfl_sync(FULL_MASK, lo ? b_lo : b_hi, src);

        const unsigned vu = __ldg(reinterpret_cast<const unsigned*>(
                                      tab + (size_t)iu * 64 + coff));
        const unsigned vb = __ldg(reinterpret_cast<const unsigned*>(
                                      tab + (size_t)ib * 64 + coff));

        au.x += __uint_as_float(vu << 16);            // even dim (low bf16)
        au.y += __uint_as_float(vu & 0xFFFF0000u);    // odd dim  (high bf16)
        ai.x += __uint_as_float(vb << 16);
        ai.y += __uint_as_float(vb & 0xFFFF0000u);
    }

    // Reduce au across the 2 groups (stride 16): lanes with equal c now
    // hold full u values; c==8 lanes hold (su, 0).
    au.x += __shfl_xor_sync(FULL_MASK, au.x, 16);
    au.y += __shfl_xor_sync(FULL_MASK, au.y, 16);

    // Unnormalized dot(u, i): ai stays per-group partial, so summing over
    // all 32 lanes counts each (c, g) cell exactly once. Exclude c==8
    // (escore lane) -- c 9..15 are zeros anyway.
    float r = (c < 8) ? (au.x * ai.x + au.y * ai.y) : 0.f;
    #pragma unroll
    for (int off = 16; off; off >>= 1)
        r += __shfl_xor_sync(FULL_MASK, r, off);

    // Denominators: su already group-reduced in au.x at c==8;
    // si = group-reduced ai.x at c==8.
    float t = ai.x;
    t += __shfl_xor_sync(FULL_MASK, t, 16);
    const float su = __shfl_sync(FULL_MASK, au.x, 8);
    const float si = __shfl_sync(FULL_MASK, t,    8);

    if (lane == 0) {
        // All-pad row: su/si == 0 -> inv = 0 matches the reference
        // (it pools the all-zero PAD embedding row).
        const float inv_u = (su > 0.f) ? (1.0f / su) : 0.f;
        const float inv_i = (si > 0.f) ? (1.0f / si) : 0.f;
        out[row] = r * inv_u * inv_i
                 + __ldg(user_bias + __ldg(user_idx + row))
                 + __ldg(item_bias + __ldg(item_idx + row))
                 + __ldg(global_bias);
    }
}

extern "C" void kernel_launch(void* const* d_in, const int* in_sizes, int n_in,
                              void* d_out, int out_size)
{
    const float* subj_emb    = (const float*)d_in[0];
    const float* attn_w      = (const float*)d_in[1];
    const float* attn_b      = (const float*)d_in[2];
    const float* user_bias   = (const float*)d_in[3];
    const float* item_bias   = (const float*)d_in[4];
    const float* global_bias = (const float*)d_in[5];
    const int*   user_idx    = (const int*)d_in[6];
    const int*   item_idx    = (const int*)d_in[7];
    const int*   fav         = (const int*)d_in[8];
    const int*   book        = (const int*)d_in[9];
    float*       out         = (float*)d_out;

    tab_kernel<<<(N_SUBJECTS + 255) / 256, 256>>>(subj_emb, attn_w, attn_b);

    const int threads = 256;                       // 8 warps = 8 rows/block
    const int blocks  = (B_ROWS * 32) / threads;   // 2048
    scalar_pooler_kernel<<<blocks, threads>>>(
        user_bias, item_bias, global_bias,
        user_idx, item_idx, fav, book, out);
}

// round 12
// speedup vs baseline: 1.1254x; 1.1254x over previous
#include <cuda_runtime.h>
#include <cuda_bf16.h>

#define FULL_MASK 0xFFFFFFFFu

constexpr int B_ROWS     = 16384;
constexpr int SEQ_L      = 50;
constexpr int N_SUBJECTS = 10000;
constexpr int N_ITER     = 13;      // 13 * 4 groups = 52 >= 50 positions

// Augmented bf16 table, one 64B row per subject:
//   bytes [0,32):  escore_j * emb_j  as 16 bf16
//   bytes [32,34): escore_j as bf16
//   bytes [34,64): zeros
// escore_j = exp(dot(emb_j, w) + b); escore_0 := 0 so PAD (idx 0) and
// out-of-range positions contribute 0 to numerator AND denominator.
// Softmax without max-subtraction is exact: scores are O(0.1)
// (emb ~0.1*N, w ~0.25*N, D=16) -> no fp32 overflow; shift-invariant.
__device__ __align__(128) uint4 g_tab[N_SUBJECTS * 4];

__device__ __forceinline__ float dot4(float4 a, float4 b) {
    return a.x * b.x + a.y * b.y + a.z * b.z + a.w * b.w;
}

// ---------------- Prologue: build augmented bf16 table ----------------
__global__ void __launch_bounds__(256)
tab_kernel(const float* __restrict__ subj_emb,
           const float* __restrict__ attn_w,
           const float* __restrict__ attn_b)
{
    const int j = blockIdx.x * blockDim.x + threadIdx.x;
    if (j >= N_SUBJECTS) return;

    const float4* wp = reinterpret_cast<const float4*>(attn_w);
    const float4 w0 = __ldg(wp + 0), w1 = __ldg(wp + 1),
                 w2 = __ldg(wp + 2), w3 = __ldg(wp + 3);

    const float4* ep = reinterpret_cast<const float4*>(subj_emb) + (size_t)j * 4;
    const float4 e0 = __ldg(ep + 0), e1 = __ldg(ep + 1),
                 e2 = __ldg(ep + 2), e3 = __ldg(ep + 3);

    const float s = dot4(e0, w0) + dot4(e1, w1) + dot4(e2, w2) + dot4(e3, w3)
                  + __ldg(attn_b);
    const float w = (j == 0) ? 0.0f : __expf(s);

    const float4 p0 = make_float4(w*e0.x, w*e0.y, w*e0.z, w*e0.w);
    const float4 p1 = make_float4(w*e1.x, w*e1.y, w*e1.z, w*e1.w);
    const float4 p2 = make_float4(w*e2.x, w*e2.y, w*e2.z, w*e2.w);
    const float4 p3 = make_float4(w*e3.x, w*e3.y, w*e3.z, w*e3.w);

    auto pack2 = [](float a, float b) -> unsigned {
        __nv_bfloat162 h = __floats2bfloat162_rn(a, b);
        return *reinterpret_cast<unsigned*>(&h);
    };

    uint4* dst = g_tab + (size_t)j * 4;
    dst[0] = make_uint4(pack2(p0.x,p0.y), pack2(p0.z,p0.w),
                        pack2(p1.x,p1.y), pack2(p1.z,p1.w));
    dst[1] = make_uint4(pack2(p2.x,p2.y), pack2(p2.z,p2.w),
                        pack2(p3.x,p3.y), pack2(p3.z,p3.w));
    dst[2] = make_uint4(pack2(w, 0.f), 0u, 0u, 0u);   // escore slot
    dst[3] = make_uint4(0u, 0u, 0u, 0u);
}

// ---------------- Main: warp per row, 4 groups x 8 lanes ----------------
// Group g handles positions p = it*4 + g. Lane c = lane&7:
//   c 0..3 -> LDG.64 of premult bf16 chunk c (8B = 4 values)
//   c 4..7 -> LDG.64 at offset 32 -> [escore, 0, 0, 0]
// Explicit depth-2 software pipeline: iteration n+1's two LDG.64s are
// issued before iteration n is consumed, so >=4 loads stay in flight per
// warp (R8 was L2-latency bound at ~2). launch_bounds(256,5) grants ~51
// regs so ptxas can hold the staging registers without spilling.
__global__ void __launch_bounds__(256, 5)
scalar_pooler_kernel(
    const float* __restrict__ user_bias,
    const float* __restrict__ item_bias,
    const float* __restrict__ global_bias,
    const int*   __restrict__ user_idx,
    const int*   __restrict__ item_idx,
    const int*   __restrict__ fav,
    const int*   __restrict__ book,
    float*       __restrict__ out)
{
    const int row  = (blockIdx.x * blockDim.x + threadIdx.x) >> 5;
    const int lane = threadIdx.x & 31;
    const int grp  = lane >> 3;                    // 0..3
    const int c    = lane & 7;                     // 0..7
    if (row >= B_ROWS) return;

    const int offc = (c < 4) ? c * 8 : 32;         // byte offset within row
    const char* tabc = reinterpret_cast<const char*>(g_tab) + offc;

    const int* frow = fav  + (size_t)row * SEQ_L;
    const int* brow = book + (size_t)row * SEQ_L;

    // Coalesced index preload; OOB (>=50) reads as 0 -> zero table row.
    // Pre-shift by 6 so shfl delivers ready byte offsets (row stride 64).
    const int f_lo = __ldg(frow + lane) << 6;
    const int f_hi = ((lane + 32 < SEQ_L) ? __ldg(frow + lane + 32) : 0) << 6;
    const int b_lo = __ldg(brow + lane) << 6;
    const int b_hi = ((lane + 32 < SEQ_L) ? __ldg(brow + lane + 32) : 0) << 6;

    float4 au = make_float4(0.f, 0.f, 0.f, 0.f);
    float4 ai = make_float4(0.f, 0.f, 0.f, 0.f);

    // --- software pipeline, depth 2 ---
    uint2 ru_cur, rb_cur;
    {
        const int ou = __shfl_sync(FULL_MASK, f_lo, grp);   // it=0: src=grp
        const int ob = __shfl_sync(FULL_MASK, b_lo, grp);
        ru_cur = __ldg(reinterpret_cast<const uint2*>(tabc + (size_t)(unsigned)ou));
        rb_cur = __ldg(reinterpret_cast<const uint2*>(tabc + (size_t)(unsigned)ob));
    }

    #pragma unroll
    for (int it = 0; it < N_ITER; it++) {
        uint2 ru_nxt, rb_nxt;
        if (it + 1 < N_ITER) {                      // compile-time per copy
            const int n   = it + 1;
            const int src = ((n < 8) ? n : (n - 8)) * 4 + grp;
            const int ou  = __shfl_sync(FULL_MASK, (n < 8) ? f_lo : f_hi, src);
            const int ob  = __shfl_sync(FULL_MASK, (n < 8) ? b_lo : b_hi, src);
            ru_nxt = __ldg(reinterpret_cast<const uint2*>(tabc + (size_t)(unsigned)ou));
            rb_nxt = __ldg(reinterpret_cast<const uint2*>(tabc + (size_t)(unsigned)ob));
        }

        // consume current (bf16 -> f32 via shift/mask; bf16 = top fp32 bits)
        au.x += __uint_as_float(ru_cur.x << 16);
        au.y += __uint_as_float(ru_cur.x & 0xFFFF0000u);
        au.z += __uint_as_float(ru_cur.y << 16);
        au.w += __uint_as_float(ru_cur.y & 0xFFFF0000u);
        ai.x += __uint_as_float(rb_cur.x << 16);
        ai.y += __uint_as_float(rb_cur.x & 0xFFFF0000u);
        ai.z += __uint_as_float(rb_cur.y << 16);
        ai.w += __uint_as_float(rb_cur.y & 0xFFFF0000u);

        ru_cur = ru_nxt;  rb_cur = rb_nxt;
    }

    // Reduce au across the 4 groups (lane = grp*8 + c; strides 8, 16).
    // Afterwards: c 0..3 hold u numerator chunks, c==4 holds (su,0,0,0).
    #pragma unroll
    for (int off = 8; off < 32; off <<= 1) {
        au.x += __shfl_xor_sync(FULL_MASK, au.x, off);
        au.y += __shfl_xor_sync(FULL_MASK, au.y, off);
        au.z += __shfl_xor_sync(FULL_MASK, au.z, off);
        au.w += __shfl_xor_sync(FULL_MASK, au.w, off);
    }

    // Unnormalized dot(u, i): ai is still per-(group, chunk) partial, so the
    // 32-lane sum counts each cell exactly once; exclude escore lanes.
    float r = (c < 4) ? dot4(au, ai) : 0.f;
    #pragma unroll
    for (int off = 16; off; off >>= 1)
        r += __shfl_xor_sync(FULL_MASK, r, off);

    // Denominators: si = group-reduced ai.x at c==4; su already in au.x.
    float t = ai.x;
    t += __shfl_xor_sync(FULL_MASK, t, 8);
    t += __shfl_xor_sync(FULL_MASK, t, 16);

    const float su = __shfl_sync(FULL_MASK, au.x, 4);
    const float si = __shfl_sync(FULL_MASK, t,    4);

    if (lane == 0) {
        // All-pad row: su/si == 0 -> inv = 0 matches the reference
        // (it pools the all-zero PAD embedding row).
        const float inv_u = (su > 0.f) ? (1.0f / su) : 0.f;
        const float inv_i = (si > 0.f) ? (1.0f / si) : 0.f;
        out[row] = r * inv_u * inv_i
                 + __ldg(user_bias + __ldg(user_idx + row))
                 + __ldg(item_bias + __ldg(item_idx + row))
                 + __ldg(global_bias);
    }
}

extern "C" void kernel_launch(void* const* d_in, const int* in_sizes, int n_in,
                              void* d_out, int out_size)
{
    const float* subj_emb    = (const float*)d_in[0];
    const float* attn_w      = (const float*)d_in[1];
    const float* attn_b      = (const float*)d_in[2];
    const float* user_bias   = (const float*)d_in[3];
    const float* item_bias   = (const float*)d_in[4];
    const float* global_bias = (const float*)d_in[5];
    const int*   user_idx    = (const int*)d_in[6];
    const int*   item_idx    = (const int*)d_in[7];
    const int*   fav         = (const int*)d_in[8];
    const int*   book        = (const int*)d_in[9];
    float*       out         = (float*)d_out;

    tab_kernel<<<(N_SUBJECTS + 255) / 256, 256>>>(subj_emb, attn_w, attn_b);

    const int threads = 256;                       // 8 warps = 8 rows/block
    const int blocks  = (B_ROWS * 32) / threads;   // 2048
    scalar_pooler_kernel<<<blocks, threads>>>(
        user_bias, item_bias, global_bias,
        user_idx, item_idx, fav, book, out);
}